// round 11
// baseline (speedup 1.0000x reference)
#include <cuda_runtime.h>
#include <math.h>

#define TPB 256
#define TS 32
#define NT1 4096
#define NT2 1024
#define Y1MAX 6.08f
#define NK_HALF 2456   // half-space of 17^3 grid (indices past center)
#define KPW 2          // k-vectors per recip warp
#define NB_RECIP 154   // 154 * 8 warps * 2 k = 2464 >= 2456
#define FULLMASK 0xffffffffu

__device__ float2 g_T1[NT1];   // erfc(y), y in [0, Y1MAX]
__device__ float2 g_T2[NT2];   // erfc(r*inve)/r indexed by r^2 in [0, cutr2]

struct AccT {
    double r[32];
    double k[32];
    unsigned int cnt;
    unsigned int pad[31];
};
__device__ AccT g_acc;   // zero at load; self-resetting per run

__device__ __forceinline__ float blockReduceF(float v) {
    __shared__ float sh[32];
    int lane = threadIdx.x & 31, w = threadIdx.x >> 5;
    #pragma unroll
    for (int o = 16; o; o >>= 1) v += __shfl_down_sync(FULLMASK, v, o);
    if (lane == 0) sh[w] = v;
    __syncthreads();
    if (w == 0) {
        v = (lane < (TPB >> 5)) ? sh[lane] : 0.f;
        #pragma unroll
        for (int o = 16; o; o >>= 1) v += __shfl_down_sync(FULLMASK, v, o);
    }
    return v;
}

// cheap eta: (vol^2/n)^(1/6) / sqrt(2*pi) via MUFU log/exp (rel err ~1e-6)
__device__ __forceinline__ float fast_eta(float vol, int n) {
    return __expf(__logf(vol * vol / (float)n) * 0.16666667f) * 0.39894228040143267f;
}

// AS 7.1.26 erfc (generic slow path only)
__device__ __forceinline__ float erfc_as(float x) {
    float t = __fdividef(1.0f, fmaf(0.3275911f, x, 1.0f));
    float p = t * fmaf(t, fmaf(t, fmaf(t, fmaf(t, 1.061405429f, -1.453152027f),
              1.421413741f), -0.284496736f), 0.254829592f);
    return p * __expf(-x * x);
}

// linear-interp table lookup; x is pre-scaled index
__device__ __forceinline__ float lut(const float2* __restrict__ T, float x, int nmax) {
    x = fminf(x, (float)(nmax - 1) - 1e-3f);
    int idx = (int)x;
    float fr = x - (float)idx;
    float2 e = T[idx];
    return fmaf(fr, e.y, e.x);
}

// ---------------- table build (runs before k_main each replay) --------------
__global__ void k_tables(const float* __restrict__ cell, int n) {
    float c00 = __ldg(cell + 0), c01 = __ldg(cell + 1), c02 = __ldg(cell + 2);
    float c10 = __ldg(cell + 3), c11 = __ldg(cell + 4), c12 = __ldg(cell + 5);
    float c20 = __ldg(cell + 6), c21 = __ldg(cell + 7), c22 = __ldg(cell + 8);
    float det = c00 * (c11 * c22 - c12 * c21)
              - c01 * (c10 * c22 - c12 * c20)
              + c02 * (c10 * c21 - c11 * c20);
    float vol = fabsf(det);
    float eta = fast_eta(vol, n);
    float cutr = 6.0697085114f * eta;
    float cutr2 = cutr * cutr;
    float inve = 0.7071067811865476f / eta;

    int t = blockIdx.x * blockDim.x + threadIdx.x;
    if (t < NT1) {
        float dy = Y1MAX / (float)NT1;
        float f0 = erfcf(t * dy);
        float f1 = erfcf((t + 1) * dy);
        g_T1[t] = make_float2(f0, f1 - f0);
    } else if (t < NT1 + NT2) {
        int i = t - NT1;
        float du = cutr2 / (float)NT2;
        float u0 = i * du, u1 = u0 + du;
        float f0 = 0.f, f1 = 0.f;
        if (i > 0)        { float r0 = sqrtf(u0); f0 = erfcf(r0 * inve) / r0; }
        if (i + 1 < NT2)  { float r1 = sqrtf(u1); f1 = erfcf(r1 * inve) / r1; }
        g_T2[i] = make_float2(f0, f1 - f0);    // top entry -> 0 (cutoff)
    }
}

__global__ void __launch_bounds__(TPB, 4)
k_main(const float* __restrict__ pos, const float* __restrict__ cell,
       const float* __restrict__ q, const float* __restrict__ sigt,
       const int* __restrict__ spec, const int* __restrict__ nsr,
       const int* __restrict__ nkr, float* __restrict__ out,
       int n, unsigned int total_blocks) {
    __shared__ float2 sT1[NT1];
    __shared__ float2 sT2[NT2];
    __shared__ float4 sj_pq[TS];
    __shared__ float  sj_s2[TS];
    int tid = threadIdx.x;
    int b = blockIdx.x;

    float c00 = __ldg(cell + 0), c01 = __ldg(cell + 1), c02 = __ldg(cell + 2);
    float c10 = __ldg(cell + 3), c11 = __ldg(cell + 4), c12 = __ldg(cell + 5);
    float c20 = __ldg(cell + 6), c21 = __ldg(cell + 7), c22 = __ldg(cell + 8);
    float det = c00 * (c11 * c22 - c12 * c21)
              - c01 * (c10 * c22 - c12 * c20)
              + c02 * (c10 * c21 - c11 * c20);
    float vol = fabsf(det);
    float eta = fast_eta(vol, n);
    const float SQRT_2LOG = 6.0697085114f;
    float cutr = SQRT_2LOG * eta;
    float cutr2 = cutr * cutr;
    float inve = 0.7071067811865476f / eta;

    if (b < NB_RECIP) {
        // ---------- reciprocal: KPW half-space k-vectors per warp ------------
        int w = tid >> 5, lane = tid & 31;
        const float TWO_PI = 6.283185307179586f;
        float cutk = SQRT_2LOG / eta;
        float id = __fdividef(TWO_PI, det);
        int nk = __ldg(nkr);
        for (int kk = 0; kk < KPW; ++kk) {
            int widx = (b * 8 + w) * KPW + kk;
            if (widx >= NK_HALF) break;
            int f = 2457 + widx;
            int kx = f % 17 - 8;
            int ky = (f / 17) % 17 - 8;
            int kz = f / 289 - 8;
            if (abs(kx) > nk || abs(ky) > nk || abs(kz) > nk) continue;
            float kax = (kx*(c11*c22-c12*c21) + ky*(c12*c20-c10*c22) + kz*(c10*c21-c11*c20)) * id;
            float kay = (kx*(c02*c21-c01*c22) + ky*(c00*c22-c02*c20) + kz*(c01*c20-c00*c21)) * id;
            float kaz = (kx*(c01*c12-c02*c11) + ky*(c02*c10-c00*c12) + kz*(c00*c11-c01*c10)) * id;
            float k2 = kax*kax + kay*kay + kaz*kaz;
            if (k2 <= 1e-16f || k2 >= cutk * cutk) continue;
            float wgt = __fdividef(__expf(-0.5f * eta * eta * k2), k2);
            float sc = 0.f, ss = 0.f;
            for (int i2 = lane; i2 < n; i2 += 32) {
                float th = fmaf(kax, __ldg(pos+3*i2),
                           fmaf(kay, __ldg(pos+3*i2+1), kaz * __ldg(pos+3*i2+2)));
                th -= TWO_PI * rintf(th * 0.15915494309189535f);
                float s, c;
                __sincosf(th, &s, &c);
                float qv = __ldg(q + i2);
                sc = fmaf(qv, c, sc);
                ss = fmaf(qv, s, ss);
            }
            #pragma unroll
            for (int o = 16; o; o >>= 1) {
                sc += __shfl_down_sync(FULLMASK, sc, o);
                ss += __shfl_down_sync(FULLMASK, ss, o);
            }
            if (lane == 0)
                atomicAdd(&g_acc.k[widx & 31], (double)(2.0f * wgt * (sc*sc + ss*ss)));
        }
    } else {
        // ---------- real space: one block per ordered 32x32 tile pair --------
        int bt = b - NB_RECIP;
        int ti = (int)(sqrtf(2.0f * (float)bt + 0.25f) - 0.5f);
        if ((ti + 1) * (ti + 2) / 2 <= bt) ++ti;
        if (ti * (ti + 1) / 2 > bt) --ti;
        int tj = bt - ti * (ti + 1) / 2;     // tj <= ti

        // stage erfc tables + j-tile
        for (int t2 = tid; t2 < NT1; t2 += TPB) sT1[t2] = g_T1[t2];
        for (int t2 = tid; t2 < NT2; t2 += TPB) sT2[t2] = g_T2[t2];
        if (tid < TS) {
            int a = tj * TS + tid;
            if (a < n) {
                sj_pq[tid] = make_float4(__ldg(pos+3*a), __ldg(pos+3*a+1),
                                         __ldg(pos+3*a+2), __ldg(q+a));
                float sg = __ldg(sigt + __ldg(spec + a));
                sj_s2[tid] = 2.0f * sg * sg;
            } else {
                sj_pq[tid] = make_float4(0.f, 0.f, 0.f, 0.f);
                sj_s2[tid] = 1.0f;
            }
        }
        __syncthreads();

        int li = tid & 31;
        int i = ti * TS + li;
        bool iok = (i < n);
        int ic = iok ? i : 0;
        float pix = __ldg(pos + 3*ic), piy = __ldg(pos + 3*ic + 1), piz = __ldg(pos + 3*ic + 2);
        float qi  = __ldg(q + ic);
        float sgi = __ldg(sigt + __ldg(spec + ic));
        float s2i = 2.0f * sgi * sgi;

        int jj0 = (tid >> 5) * 4;
        float local = 0.f;

        int ns = __ldg(nsr);
        bool diag = (c01==0.f && c02==0.f && c10==0.f && c12==0.f && c20==0.f && c21==0.f);
        bool fast = diag && ns >= 1 &&
                    cutr2 <= c00*c00 && cutr2 <= c11*c11 && cutr2 <= c22*c22;

        if (fast) {   // warp-uniform
            float iLx = __fdividef(1.0f, c00);
            float iLy = __fdividef(1.0f, c11);
            float iLz = __fdividef(1.0f, c22);
            const float scale1 = (float)NT1 / Y1MAX;
            float scale2 = __fdividef((float)NT2, cutr2);

            #pragma unroll
            for (int u = 0; u < 4; ++u) {
                int jl = jj0 + u;
                int j = tj * TS + jl;
                float4 Pj = sj_pq[jl];
                float s2j = sj_s2[jl];
                float wgt = 0.f;
                if (iok && j < n)
                    wgt = (ti != tj) ? 2.0f : ((j < i) ? 2.0f : ((j == i) ? 1.0f : 0.0f));
                float qq = wgt * qi * Pj.w;

                float dx = Pj.x - pix, dy = Pj.y - piy, dz = Pj.z - piz;
                float invg  = rsqrtf(s2i + s2j);
                float invg2 = invg * invg;

                float x0 = fmaf(-c00, rintf(dx * iLx), dx);
                float y0 = fmaf(-c11, rintf(dy * iLy), dy);
                float z0 = fmaf(-c22, rintf(dz * iLz), dz);
                float x1 = x0 - copysignf(c00, x0);
                float y1 = y0 - copysignf(c11, y0);
                float z1 = z0 - copysignf(c22, z0);
                float xs0 = x0*x0, xs1 = x1*x1;
                float ys0 = y0*y0, ys1 = y1*y1;
                float zs0 = z0*z0, zs1 = z1*z1;

                // min image: two erfc lookups, one rsqrt
                {
                    float r2 = xs0 + ys0 + zs0;
                    float r2s = fmaxf(r2, 1e-12f);
                    float rinv = rsqrtf(r2s);
                    float r = r2s * rinv;
                    float vA = lut(sT1, r * inve * scale1, NT1);
                    float vB = lut(sT1, r * invg * scale1, NT1);
                    float okq = (r2 > 1e-16f && r2 < cutr2) ? qq : 0.f;
                    local = fmaf(okq, (vA - vB) * rinv, local);
                }
                // secondary images: branch-free T2 lookups, ZERO MUFU
                #pragma unroll
                for (int c = 1; c < 8; ++c) {
                    float r2 = ((c & 1) ? xs1 : xs0) + ((c & 2) ? ys1 : ys0)
                             + ((c & 4) ? zs1 : zs0);
                    float v = lut(sT2, r2 * scale2, NT2);
                    if (r2 * invg2 < 37.f && r2 < cutr2) {  // gamma non-negligible: ~never
                        float rinv = rsqrtf(r2);
                        v -= lut(sT1, r2 * rinv * invg * scale1, NT1) * rinv;
                    }
                    local = fmaf(qq, v, local);
                }
            }
        } else {
            #pragma unroll 1
            for (int u = 0; u < 4; ++u) {
                int jl = jj0 + u;
                int j = tj * TS + jl;
                float4 Pj = sj_pq[jl];
                float s2j = sj_s2[jl];
                float wgt = 0.f;
                if (iok && j < n)
                    wgt = (ti != tj) ? 2.0f : ((j < i) ? 2.0f : ((j == i) ? 1.0f : 0.0f));
                float qq = wgt * qi * Pj.w;
                float dx = Pj.x - pix, dy = Pj.y - piy, dz = Pj.z - piz;
                float invg = rsqrtf(s2i + s2j);

                for (int sx = -ns; sx <= ns; ++sx)
                    for (int sy = -ns; sy <= ns; ++sy) {
                        float bx = dx + sx*c00 + sy*c10;
                        float by = dy + sx*c01 + sy*c11;
                        float bz = dz + sx*c02 + sy*c12;
                        for (int sz = -ns; sz <= ns; ++sz) {
                            float ax = bx + sz*c20, ay = by + sz*c21, az = bz + sz*c22;
                            float r2 = ax*ax + ay*ay + az*az;
                            if (r2 > 1e-16f && r2 < cutr2) {
                                float rinv = rsqrtf(r2);
                                float r = r2 * rinv;
                                local += qq * (erfc_as(r*inve) - erfc_as(r*invg)) * rinv;
                            }
                        }
                    }
            }
        }
        float tot = blockReduceF(local);
        if (tid == 0) atomicAdd(&g_acc.r[b & 31], (double)tot);
    }

    // ---------------- last block: self term + combine + RESET ---------------
    __shared__ bool isLast;
    __syncthreads();
    if (tid == 0) {
        __threadfence();
        unsigned int prev = atomicAdd(&g_acc.cnt, 1u);
        isLast = (prev == total_blocks - 1);
    }
    __syncthreads();
    if (!isLast) return;

    __shared__ double shd[64];
    if (tid < 64)
        shd[tid] = (tid < 32) ? __ldcg(&g_acc.r[tid]) : __ldcg(&g_acc.k[tid - 32]);
    __syncthreads();

    if (tid < 32) { g_acc.r[tid] = 0.0; g_acc.k[tid] = 0.0; }
    if (tid == 0) g_acc.cnt = 0u;

    float a = -0.7978845608028654f / eta;
    float selfLocal = 0.f;
    for (int i2 = tid; i2 < n; i2 += TPB) {
        float qv = __ldg(q + i2);
        float sg = __ldg(sigt + __ldg(spec + i2));
        selfLocal += qv * qv * (a + 0.5641895835477563f / sg);
    }
    float selfSum = blockReduceF(selfLocal);
    if (tid == 0) {
        double sr = 0.0, sk = 0.0;
        #pragma unroll
        for (int tt = 0; tt < 32; ++tt) { sr += shd[tt]; sk += shd[32 + tt]; }
        const double COEF = 14.399645478425668;
        double E = 0.5 * COEF * (sr + (4.0 * M_PI / (double)vol) * sk + (double)selfSum);
        out[0] = (float)E;
    }
}

extern "C" void kernel_launch(void* const* d_in, const int* in_sizes, int n_in,
                              void* d_out, int out_size) {
    const float* pos  = (const float*)d_in[0];
    const float* cell = (const float*)d_in[1];
    const float* q    = (const float*)d_in[2];
    const float* sigt = (const float*)d_in[3];
    const int*   spec = (const int*)d_in[4];
    const int*   nsr  = (const int*)d_in[5];
    const int*   nkr  = (const int*)d_in[6];
    int n = in_sizes[0] / 3;

    k_tables<<<(NT1 + NT2 + TPB - 1) / TPB, TPB>>>(cell, n);

    int nt = (n + TS - 1) / TS;
    int nTilePairs = nt * (nt + 1) / 2;
    unsigned int total = NB_RECIP + nTilePairs;
    k_main<<<total, TPB>>>(pos, cell, q, sigt, spec, nsr, nkr,
                           (float*)d_out, n, total);
}

// round 12
// speedup vs baseline: 1.4414x; 1.4414x over previous
#include <cuda_runtime.h>
#include <math.h>

#define TPB 256
#define TS 32
#define NT1 4096
#define NT2 1024
#define Y1MAX 6.08f
#define MAXA 1024
#define NK_HALF 2456   // half-space of 17^3 grid (indices past center)
#define KPW 2          // k-vectors per recip warp
#define NB_RECIP 154   // 154 * 8 * 2 = 2464 >= 2456
#define FULLMASK 0xffffffffu

__device__ float2 g_T1[NT1];   // erfc(y), y in [0, Y1MAX]
__device__ float2 g_T2[NT2];   // erfc(r*inve)/r indexed by r^2 in [0, cutr2]

struct AccT {
    double r[32];
    double k[32];
    unsigned int cnt;
    unsigned int pad[31];
};
__device__ AccT g_acc;   // zero at load; self-resetting per run

__device__ __forceinline__ float blockReduceF(float v) {
    __shared__ float sh[32];
    int lane = threadIdx.x & 31, w = threadIdx.x >> 5;
    #pragma unroll
    for (int o = 16; o; o >>= 1) v += __shfl_down_sync(FULLMASK, v, o);
    if (lane == 0) sh[w] = v;
    __syncthreads();
    if (w == 0) {
        v = (lane < (TPB >> 5)) ? sh[lane] : 0.f;
        #pragma unroll
        for (int o = 16; o; o >>= 1) v += __shfl_down_sync(FULLMASK, v, o);
    }
    return v;
}

__device__ __forceinline__ float fast_eta(float vol, int n) {
    return __expf(__logf(vol * vol / (float)n) * 0.16666667f) * 0.39894228040143267f;
}

// AS 7.1.26 erfc (generic slow path only)
__device__ __forceinline__ float erfc_as(float x) {
    float t = __fdividef(1.0f, fmaf(0.3275911f, x, 1.0f));
    float p = t * fmaf(t, fmaf(t, fmaf(t, fmaf(t, 1.061405429f, -1.453152027f),
              1.421413741f), -0.284496736f), 0.254829592f);
    return p * __expf(-x * x);
}

// linear-interp lookup from GLOBAL table (L1-cached), pre-scaled index
__device__ __forceinline__ float lutg(const float2* __restrict__ T, float x, int nmax) {
    x = fminf(fmaxf(x, 0.f), (float)(nmax - 1) - 1e-3f);
    int idx = (int)x;
    float fr = x - (float)idx;
    float2 e = __ldg(&T[idx]);
    return fmaf(fr, e.y, e.x);
}

// ---------------- table build (cheap, once per replay) ----------------------
__global__ void k_tables(const float* __restrict__ cell, int n) {
    float c00 = __ldg(cell + 0), c11 = __ldg(cell + 4), c22 = __ldg(cell + 8);
    float c01 = __ldg(cell + 1), c02 = __ldg(cell + 2), c10 = __ldg(cell + 3);
    float c12 = __ldg(cell + 5), c20 = __ldg(cell + 6), c21 = __ldg(cell + 7);
    float det = c00 * (c11 * c22 - c12 * c21)
              - c01 * (c10 * c22 - c12 * c20)
              + c02 * (c10 * c21 - c11 * c20);
    float vol = fabsf(det);
    float eta = fast_eta(vol, n);
    float cutr = 6.0697085114f * eta;
    float cutr2 = cutr * cutr;
    float inve = 0.7071067811865476f / eta;

    int t = blockIdx.x * blockDim.x + threadIdx.x;
    if (t < NT1) {
        float dy = Y1MAX / (float)NT1;
        float f0 = erfcf(t * dy);
        float f1 = erfcf((t + 1) * dy);
        g_T1[t] = make_float2(f0, f1 - f0);
    } else if (t < NT1 + NT2) {
        int i = t - NT1;
        float du = cutr2 / (float)NT2;
        float u0 = i * du, u1 = u0 + du;
        float f0 = 0.f, f1 = 0.f;
        if (i > 0)       { float r0 = sqrtf(u0); f0 = erfcf(r0 * inve) / r0; }
        if (i + 1 < NT2) { float r1 = sqrtf(u1); f1 = erfcf(r1 * inve) / r1; }
        g_T2[i] = make_float2(f0, f1 - f0);
    }
}

__global__ void __launch_bounds__(TPB)
k_main(const float* __restrict__ pos, const float* __restrict__ cell,
       const float* __restrict__ q, const float* __restrict__ sigt,
       const int* __restrict__ spec, const int* __restrict__ nsr,
       const int* __restrict__ nkr, float* __restrict__ out,
       int n, unsigned int total_blocks) {
    __shared__ float4 s_at[MAXA];       // recip: staged atoms (x,y,z,q)
    __shared__ float4 sj_pq[TS];        // real: j-tile (x,y,z, staged-weighted q)
    __shared__ float  sj_s2[TS];
    int tid = threadIdx.x;
    int b = blockIdx.x;

    float c00 = __ldg(cell + 0), c01 = __ldg(cell + 1), c02 = __ldg(cell + 2);
    float c10 = __ldg(cell + 3), c11 = __ldg(cell + 4), c12 = __ldg(cell + 5);
    float c20 = __ldg(cell + 6), c21 = __ldg(cell + 7), c22 = __ldg(cell + 8);
    float det = c00 * (c11 * c22 - c12 * c21)
              - c01 * (c10 * c22 - c12 * c20)
              + c02 * (c10 * c21 - c11 * c20);
    float vol = fabsf(det);
    float eta = fast_eta(vol, n);
    const float SQRT_2LOG = 6.0697085114f;
    float cutr = SQRT_2LOG * eta;
    float cutr2 = cutr * cutr;
    float inve = 0.7071067811865476f / eta;

    if (b < NB_RECIP) {
        // ---------- reciprocal: stage atoms once, KPW k's per warp -----------
        for (int a = tid; a < n && a < MAXA; a += TPB)
            s_at[a] = make_float4(__ldg(pos+3*a), __ldg(pos+3*a+1),
                                  __ldg(pos+3*a+2), __ldg(q+a));
        __syncthreads();

        int w = tid >> 5, lane = tid & 31;
        const float TWO_PI = 6.283185307179586f;
        float cutk2 = (SQRT_2LOG / eta) * (SQRT_2LOG / eta);
        float id = __fdividef(TWO_PI, det);
        int nk = __ldg(nkr);
        for (int kk = 0; kk < KPW; ++kk) {
            int widx = (b * 8 + w) * KPW + kk;
            if (widx >= NK_HALF) break;
            int f = 2457 + widx;
            int kx = f % 17 - 8;
            int ky = (f / 17) % 17 - 8;
            int kz = f / 289 - 8;
            if (abs(kx) > nk || abs(ky) > nk || abs(kz) > nk) continue;
            float kax = (kx*(c11*c22-c12*c21) + ky*(c12*c20-c10*c22) + kz*(c10*c21-c11*c20)) * id;
            float kay = (kx*(c02*c21-c01*c22) + ky*(c00*c22-c02*c20) + kz*(c01*c20-c00*c21)) * id;
            float kaz = (kx*(c01*c12-c02*c11) + ky*(c02*c10-c00*c12) + kz*(c00*c11-c01*c10)) * id;
            float k2 = kax*kax + kay*kay + kaz*kaz;
            if (k2 <= 1e-16f || k2 >= cutk2) continue;       // ~2/3 of k's exit here
            float wgt = __fdividef(__expf(-0.5f * eta * eta * k2), k2);
            float sc = 0.f, ss = 0.f;
            for (int i2 = lane; i2 < n; i2 += 32) {
                float4 p = (i2 < MAXA) ? s_at[i2]
                         : make_float4(__ldg(pos+3*i2), __ldg(pos+3*i2+1),
                                       __ldg(pos+3*i2+2), __ldg(q+i2));
                float th = fmaf(kax, p.x, fmaf(kay, p.y, kaz * p.z));
                th -= TWO_PI * rintf(th * 0.15915494309189535f);
                float s, c;
                __sincosf(th, &s, &c);
                sc = fmaf(p.w, c, sc);
                ss = fmaf(p.w, s, ss);
            }
            #pragma unroll
            for (int o = 16; o; o >>= 1) {
                sc += __shfl_down_sync(FULLMASK, sc, o);
                ss += __shfl_down_sync(FULLMASK, ss, o);
            }
            if (lane == 0)
                atomicAdd(&g_acc.k[widx & 31], (double)(2.0f * wgt * (sc*sc + ss*ss)));
        }
    } else {
        // ---------- real space: one block per ordered 32x32 tile pair --------
        int bt = b - NB_RECIP;
        int ti = (int)(sqrtf(2.0f * (float)bt + 0.25f) - 0.5f);
        if ((ti + 1) * (ti + 2) / 2 <= bt) ++ti;
        if (ti * (ti + 1) / 2 > bt) --ti;
        int tj = bt - ti * (ti + 1) / 2;     // tj <= ti
        bool diagT = (ti == tj);             // block-uniform

        if (tid < TS) {
            int a = tj * TS + tid;
            float wq = 0.f;
            float3 p = make_float3(0.f, 0.f, 0.f);
            float s2 = 1.f;
            if (a < n) {
                p = make_float3(__ldg(pos+3*a), __ldg(pos+3*a+1), __ldg(pos+3*a+2));
                wq = __ldg(q + a) * (diagT ? 1.0f : 2.0f);   // pre-fold off-diag x2
                float sg = __ldg(sigt + __ldg(spec + a));
                s2 = 2.0f * sg * sg;
            }
            sj_pq[tid] = make_float4(p.x, p.y, p.z, wq);
            sj_s2[tid] = s2;
        }
        __syncthreads();

        int li = tid & 31;
        int i = ti * TS + li;
        bool iok = (i < n);
        int ic = iok ? i : 0;
        float pix = __ldg(pos + 3*ic), piy = __ldg(pos + 3*ic + 1), piz = __ldg(pos + 3*ic + 2);
        float qi  = iok ? __ldg(q + ic) : 0.f;
        float sgi = __ldg(sigt + __ldg(spec + ic));
        float s2i = 2.0f * sgi * sgi;

        int jj0 = (tid >> 5) * 4;
        float local = 0.f;

        int ns = __ldg(nsr);
        bool diag = (c01==0.f && c02==0.f && c10==0.f && c12==0.f && c20==0.f && c21==0.f);
        bool fast = diag && ns >= 1 &&
                    cutr2 <= c00*c00 && cutr2 <= c11*c11 && cutr2 <= c22*c22;

        if (fast) {   // warp-uniform
            float iLx = __fdividef(1.0f, c00);
            float iLy = __fdividef(1.0f, c11);
            float iLz = __fdividef(1.0f, c22);
            const float scale1 = (float)NT1 / Y1MAX;
            float scale2 = __fdividef((float)NT2, cutr2);

            #pragma unroll
            for (int u = 0; u < 4; ++u) {
                int jl = jj0 + u;
                float4 Pj = sj_pq[jl];
                float s2j = sj_s2[jl];
                float qq = qi * Pj.w;
                if (diagT) {
                    int j = tj * TS + jl;
                    qq *= (j < i) ? 2.0f : ((j == i) ? 1.0f : 0.0f);
                }

                float dx = Pj.x - pix, dy = Pj.y - piy, dz = Pj.z - piz;
                float invg  = rsqrtf(s2i + s2j);
                float invg2 = invg * invg;

                float x0 = fmaf(-c00, rintf(dx * iLx), dx);
                float y0 = fmaf(-c11, rintf(dy * iLy), dy);
                float z0 = fmaf(-c22, rintf(dz * iLz), dz);
                float x1 = x0 - copysignf(c00, x0);
                float y1 = y0 - copysignf(c11, y0);
                float z1 = z0 - copysignf(c22, z0);
                float xs0 = x0*x0, xs1 = x1*x1;
                float ys0 = y0*y0, ys1 = y1*y1;
                float zs0 = z0*z0, zs1 = z1*z1;

                // min image: two T1 lookups + one rsqrt (cutoff absorbed by clamp)
                {
                    float r2 = xs0 + ys0 + zs0;
                    float rinv = rsqrtf(fmaxf(r2, 1e-12f));
                    float r = r2 * rinv;
                    float vA = lutg(g_T1, r * inve * scale1, NT1);
                    float vB = lutg(g_T1, r * invg * scale1, NT1);
                    float okq = (r2 > 1e-16f) ? qq : 0.f;
                    local = fmaf(okq, (vA - vB) * rinv, local);
                }
                // secondary images: branch-free T2, zero MUFU (gamma guard ~never taken)
                #pragma unroll
                for (int c = 1; c < 8; ++c) {
                    float r2 = ((c & 1) ? xs1 : xs0) + ((c & 2) ? ys1 : ys0)
                             + ((c & 4) ? zs1 : zs0);
                    float v = lutg(g_T2, r2 * scale2, NT2);
                    if (r2 * invg2 < 17.0f && r2 < cutr2) {
                        float ri = rsqrtf(r2);
                        v -= lutg(g_T1, r2 * ri * invg * scale1, NT1) * ri;
                    }
                    local = fmaf(qq, v, local);
                }
            }
        } else {
            #pragma unroll 1
            for (int u = 0; u < 4; ++u) {
                int jl = jj0 + u;
                int j = tj * TS + jl;
                float4 Pj = sj_pq[jl];
                float s2j = sj_s2[jl];
                float qq = qi * Pj.w;
                if (diagT) qq *= (j < i) ? 2.0f : ((j == i) ? 1.0f : 0.0f);
                float dx = Pj.x - pix, dy = Pj.y - piy, dz = Pj.z - piz;
                float invg = rsqrtf(s2i + s2j);

                for (int sx = -ns; sx <= ns; ++sx)
                    for (int sy = -ns; sy <= ns; ++sy) {
                        float bx = dx + sx*c00 + sy*c10;
                        float by = dy + sx*c01 + sy*c11;
                        float bz = dz + sx*c02 + sy*c12;
                        for (int sz = -ns; sz <= ns; ++sz) {
                            float ax = bx + sz*c20, ay = by + sz*c21, az = bz + sz*c22;
                            float r2 = ax*ax + ay*ay + az*az;
                            if (r2 > 1e-16f && r2 < cutr2) {
                                float rinv = rsqrtf(r2);
                                float r = r2 * rinv;
                                local += qq * (erfc_as(r*inve) - erfc_as(r*invg)) * rinv;
                            }
                        }
                    }
            }
        }
        float tot = blockReduceF(local);
        if (tid == 0) atomicAdd(&g_acc.r[b & 31], (double)tot);
    }

    // ---------------- last block: self term + combine + RESET ---------------
    __shared__ bool isLast;
    __syncthreads();
    if (tid == 0) {
        __threadfence();
        unsigned int prev = atomicAdd(&g_acc.cnt, 1u);
        isLast = (prev == total_blocks - 1);
    }
    __syncthreads();
    if (!isLast) return;

    __shared__ double shd[64];
    if (tid < 64)
        shd[tid] = (tid < 32) ? __ldcg(&g_acc.r[tid]) : __ldcg(&g_acc.k[tid - 32]);
    __syncthreads();

    if (tid < 32) { g_acc.r[tid] = 0.0; g_acc.k[tid] = 0.0; }
    if (tid == 0) g_acc.cnt = 0u;

    float a = -0.7978845608028654f / eta;
    float selfLocal = 0.f;
    for (int i2 = tid; i2 < n; i2 += TPB) {
        float qv = __ldg(q + i2);
        float sg = __ldg(sigt + __ldg(spec + i2));
        selfLocal += qv * qv * (a + 0.5641895835477563f / sg);
    }
    float selfSum = blockReduceF(selfLocal);
    if (tid == 0) {
        double sr = 0.0, sk = 0.0;
        #pragma unroll
        for (int tt = 0; tt < 32; ++tt) { sr += shd[tt]; sk += shd[32 + tt]; }
        const double COEF = 14.399645478425668;
        double E = 0.5 * COEF * (sr + (4.0 * M_PI / (double)vol) * sk + (double)selfSum);
        out[0] = (float)E;
    }
}

extern "C" void kernel_launch(void* const* d_in, const int* in_sizes, int n_in,
                              void* d_out, int out_size) {
    const float* pos  = (const float*)d_in[0];
    const float* cell = (const float*)d_in[1];
    const float* q    = (const float*)d_in[2];
    const float* sigt = (const float*)d_in[3];
    const int*   spec = (const int*)d_in[4];
    const int*   nsr  = (const int*)d_in[5];
    const int*   nkr  = (const int*)d_in[6];
    int n = in_sizes[0] / 3;

    k_tables<<<(NT1 + NT2 + TPB - 1) / TPB, TPB>>>(cell, n);

    int nt = (n + TS - 1) / TS;
    int nTilePairs = nt * (nt + 1) / 2;
    unsigned int total = NB_RECIP + nTilePairs;
    k_main<<<total, TPB>>>(pos, cell, q, sigt, spec, nsr, nkr,
                           (float*)d_out, n, total);
}

// round 13
// speedup vs baseline: 1.4464x; 1.0035x over previous
#include <cuda_runtime.h>
#include <math.h>

#define TPB 256
#define TS 16          // atom tile size (16x16 = 256 interactions per block)
#define MAXA 1024
#define NK_HALF 2456   // half-space of 17^3 grid (indices past center)
#define NB_RECIP 307   // 307 * 8 warps = 2456 exactly
#define FULLMASK 0xffffffffu

struct AccT {
    double r[32];
    double k[32];
    unsigned int cnt;
    unsigned int pad[31];
};
__device__ AccT g_acc;   // zero at load; self-resetting per run

__device__ __forceinline__ float blockReduceF(float v) {
    __shared__ float sh[32];
    int lane = threadIdx.x & 31, w = threadIdx.x >> 5;
    #pragma unroll
    for (int o = 16; o; o >>= 1) v += __shfl_down_sync(FULLMASK, v, o);
    if (lane == 0) sh[w] = v;
    __syncthreads();
    if (w == 0) {
        v = (lane < (TPB >> 5)) ? sh[lane] : 0.f;
        #pragma unroll
        for (int o = 16; o; o >>= 1) v += __shfl_down_sync(FULLMASK, v, o);
    }
    return v;
}

__device__ __forceinline__ float fast_eta(float vol, int n) {
    return __expf(__logf(vol * vol / (float)n) * 0.16666667f) * 0.39894228040143267f;
}

// AS 7.1.26 polynomial in t = 1/(1+0.3275911 x)
__device__ __forceinline__ float as_poly(float t) {
    return t * fmaf(t, fmaf(t, fmaf(t, fmaf(t, 1.061405429f, -1.453152027f),
           1.421413741f), -0.284496736f), 0.254829592f);
}

// full erfc (slow path only)
__device__ __forceinline__ float erfc_as(float x) {
    float t = __fdividef(1.0f, fmaf(0.3275911f, x, 1.0f));
    return as_poly(t) * __expf(-x * x);
}

__global__ void __launch_bounds__(TPB)
k_main(const float* __restrict__ pos, const float* __restrict__ cell,
       const float* __restrict__ q, const float* __restrict__ sigt,
       const int* __restrict__ spec, const int* __restrict__ nsr,
       const int* __restrict__ nkr, float* __restrict__ out,
       int n, unsigned int total_blocks) {
    __shared__ union SM {
        float4 at[MAXA];                                   // recip: staged atoms
        struct {
            float4 jt[TS]; float4 it[TS];
            float  js2[TS]; float  is2[TS];
        } t;                                               // real: tiles
    } sm;
    int tid = threadIdx.x;
    int b = blockIdx.x;

    float c00 = __ldg(cell + 0), c01 = __ldg(cell + 1), c02 = __ldg(cell + 2);
    float c10 = __ldg(cell + 3), c11 = __ldg(cell + 4), c12 = __ldg(cell + 5);
    float c20 = __ldg(cell + 6), c21 = __ldg(cell + 7), c22 = __ldg(cell + 8);
    float det = c00 * (c11 * c22 - c12 * c21)
              - c01 * (c10 * c22 - c12 * c20)
              + c02 * (c10 * c21 - c11 * c20);
    float vol = fabsf(det);
    float eta = fast_eta(vol, n);
    const float SQRT_2LOG = 6.0697085114f;
    float cutr = SQRT_2LOG * eta;
    float cutr2 = cutr * cutr;
    float inve = 0.7071067811865476f / eta;

    if (b < NB_RECIP) {
        // ---------- reciprocal: stage atoms once, one warp per k -------------
        for (int a = tid; a < n && a < MAXA; a += TPB)
            sm.at[a] = make_float4(__ldg(pos+3*a), __ldg(pos+3*a+1),
                                   __ldg(pos+3*a+2), __ldg(q+a));
        __syncthreads();

        int w = tid >> 5, lane = tid & 31;
        int widx = b * 8 + w;
        const float TWO_PI = 6.283185307179586f;
        float cutk2 = (SQRT_2LOG / eta) * (SQRT_2LOG / eta);
        int nk = __ldg(nkr);
        int f = 2457 + widx;
        int kx = f % 17 - 8;
        int ky = (f / 17) % 17 - 8;
        int kz = f / 289 - 8;
        if (abs(kx) <= nk && abs(ky) <= nk && abs(kz) <= nk) {
            float id = __fdividef(TWO_PI, det);
            float kax = (kx*(c11*c22-c12*c21) + ky*(c12*c20-c10*c22) + kz*(c10*c21-c11*c20)) * id;
            float kay = (kx*(c02*c21-c01*c22) + ky*(c00*c22-c02*c20) + kz*(c01*c20-c00*c21)) * id;
            float kaz = (kx*(c01*c12-c02*c11) + ky*(c02*c10-c00*c12) + kz*(c00*c11-c01*c10)) * id;
            float k2 = kax*kax + kay*kay + kaz*kaz;
            if (k2 > 1e-16f && k2 < cutk2) {
                float wgt = __fdividef(__expf(-0.5f * eta * eta * k2), k2);
                float sc = 0.f, ss = 0.f;
                for (int i2 = lane; i2 < n; i2 += 32) {
                    float4 p = (i2 < MAXA) ? sm.at[i2]
                             : make_float4(__ldg(pos+3*i2), __ldg(pos+3*i2+1),
                                           __ldg(pos+3*i2+2), __ldg(q+i2));
                    float th = fmaf(kax, p.x, fmaf(kay, p.y, kaz * p.z));
                    th -= TWO_PI * rintf(th * 0.15915494309189535f);
                    float s, c;
                    __sincosf(th, &s, &c);
                    sc = fmaf(p.w, c, sc);
                    ss = fmaf(p.w, s, ss);
                }
                #pragma unroll
                for (int o = 16; o; o >>= 1) {
                    sc += __shfl_down_sync(FULLMASK, sc, o);
                    ss += __shfl_down_sync(FULLMASK, ss, o);
                }
                if (lane == 0)
                    atomicAdd(&g_acc.k[widx & 31], (double)(2.0f * wgt * (sc*sc + ss*ss)));
            }
        }
    } else {
        // ---------- real space: one block per ordered 16x16 tile pair --------
        int bt = b - NB_RECIP;
        int ti = (int)(sqrtf(2.0f * (float)bt + 0.25f) - 0.5f);
        if ((ti + 1) * (ti + 2) / 2 <= bt) ++ti;
        if (ti * (ti + 1) / 2 > bt) --ti;
        int tj = bt - ti * (ti + 1) / 2;     // tj <= ti
        bool diagT = (ti == tj);             // block-uniform

        if (tid < TS) {                      // stage j-tile (weight-prefolded q)
            int a = tj * TS + tid;
            float4 v = make_float4(0.f, 0.f, 0.f, 0.f);
            float s2 = 1.f;
            if (a < n) {
                v = make_float4(__ldg(pos+3*a), __ldg(pos+3*a+1), __ldg(pos+3*a+2),
                                __ldg(q+a) * (diagT ? 1.0f : 2.0f));
                float sg = __ldg(sigt + __ldg(spec + a));
                s2 = 2.0f * sg * sg;
            }
            sm.t.jt[tid] = v; sm.t.js2[tid] = s2;
        } else if (tid < 2 * TS) {           // stage i-tile
            int li = tid - TS;
            int a = ti * TS + li;
            float4 v = make_float4(0.f, 0.f, 0.f, 0.f);
            float s2 = 1.f;
            if (a < n) {
                v = make_float4(__ldg(pos+3*a), __ldg(pos+3*a+1), __ldg(pos+3*a+2),
                                __ldg(q+a));
                float sg = __ldg(sigt + __ldg(spec + a));
                s2 = 2.0f * sg * sg;
            }
            sm.t.it[li] = v; sm.t.is2[li] = s2;
        }
        __syncthreads();

        int li = tid & (TS - 1);
        int lj = tid >> 4;                   // 0..15
        float4 Pi = sm.t.it[li]; float s2i = sm.t.is2[li];
        float4 Pj = sm.t.jt[lj]; float s2j = sm.t.js2[lj];
        float qq = Pi.w * Pj.w;
        if (diagT) {
            int i = ti * TS + li, j = tj * TS + lj;
            qq *= (j < i) ? 2.0f : ((j == i) ? 1.0f : 0.0f);
        }
        float local = 0.f;

        int ns = __ldg(nsr);
        bool diag = (c01==0.f && c02==0.f && c10==0.f && c12==0.f && c20==0.f && c21==0.f);
        bool fast = diag && ns >= 1 &&
                    cutr2 <= c00*c00 && cutr2 <= c11*c11 && cutr2 <= c22*c22;

        if (fast) {   // warp-uniform
            float iLx = __fdividef(1.0f, c00);
            float iLy = __fdividef(1.0f, c11);
            float iLz = __fdividef(1.0f, c22);
            const float L2E = 1.4426950408889634f;
            float eA = -L2E * inve * inve;

            float dx = Pj.x - Pi.x, dy = Pj.y - Pi.y, dz = Pj.z - Pi.z;
            float invg  = rsqrtf(s2i + s2j);
            float invg2 = invg * invg;
            float eB = -L2E * invg2;

            float x0 = fmaf(-c00, rintf(dx * iLx), dx);
            float y0 = fmaf(-c11, rintf(dy * iLy), dy);
            float z0 = fmaf(-c22, rintf(dz * iLz), dz);
            float x1 = x0 - copysignf(c00, x0);
            float y1 = y0 - copysignf(c11, y0);
            float z1 = z0 - copysignf(c22, z0);
            float xs0 = x0*x0, xs1 = x1*x1;
            float ys0 = y0*y0, ys1 = y1*y1;
            float zs0 = z0*z0, zs1 = z1*z1;

            // min image: both erfc chains
            {
                float r2 = xs0 + ys0 + zs0;
                if (r2 > 1e-16f && r2 < cutr2) {
                    float rinv = rsqrtf(r2);
                    float r = r2 * rinv;
                    float vA = as_poly(__frcp_rn(fmaf(0.3275911f, r * inve, 1.0f)))
                               * exp2f(r2 * eA);
                    float vB = as_poly(__frcp_rn(fmaf(0.3275911f, r * invg, 1.0f)))
                               * exp2f(r2 * eB);
                    local = fmaf(qq, (vA - vB) * rinv, local);
                }
            }
            // secondary images: lane-local mask pop, eta-chain (+ guarded gamma)
            unsigned int mask = 0u;
            #pragma unroll
            for (int c = 1; c < 8; ++c) {
                float r2 = ((c & 1) ? xs1 : xs0) + ((c & 2) ? ys1 : ys0)
                         + ((c & 4) ? zs1 : zs0);
                mask |= (r2 < cutr2 ? 1u : 0u) << c;
            }
            while (mask) {
                int c = __ffs(mask) - 1;
                mask &= mask - 1;
                float r2 = ((c & 1) ? xs1 : xs0) + ((c & 2) ? ys1 : ys0)
                         + ((c & 4) ? zs1 : zs0);
                float rinv = rsqrtf(r2);
                float r = r2 * rinv;
                float v = as_poly(__frcp_rn(fmaf(0.3275911f, r * inve, 1.0f)))
                          * exp2f(r2 * eA);
                if (r2 * invg2 < 16.5f)   // gamma-erfc non-negligible (~never: r>=L/2)
                    v -= as_poly(__frcp_rn(fmaf(0.3275911f, r * invg, 1.0f)))
                         * exp2f(r2 * eB);
                local = fmaf(qq, v * rinv, local);
            }
        } else {
            float dx = Pj.x - Pi.x, dy = Pj.y - Pi.y, dz = Pj.z - Pi.z;
            float invg = rsqrtf(s2i + s2j);
            for (int sx = -ns; sx <= ns; ++sx)
                for (int sy = -ns; sy <= ns; ++sy) {
                    float bx = dx + sx*c00 + sy*c10;
                    float by = dy + sx*c01 + sy*c11;
                    float bz = dz + sx*c02 + sy*c12;
                    for (int sz = -ns; sz <= ns; ++sz) {
                        float ax = bx + sz*c20, ay = by + sz*c21, az = bz + sz*c22;
                        float r2 = ax*ax + ay*ay + az*az;
                        if (r2 > 1e-16f && r2 < cutr2) {
                            float rinv = rsqrtf(r2);
                            float r = r2 * rinv;
                            local += qq * (erfc_as(r*inve) - erfc_as(r*invg)) * rinv;
                        }
                    }
                }
        }
        float tot = blockReduceF(local);
        if (tid == 0) atomicAdd(&g_acc.r[b & 31], (double)tot);
    }

    // ---------------- last block: self term + combine + RESET ---------------
    __shared__ bool isLast;
    __syncthreads();
    if (tid == 0) {
        __threadfence();
        unsigned int prev = atomicAdd(&g_acc.cnt, 1u);
        isLast = (prev == total_blocks - 1);
    }
    __syncthreads();
    if (!isLast) return;

    __shared__ double shd[64];
    if (tid < 64)
        shd[tid] = (tid < 32) ? __ldcg(&g_acc.r[tid]) : __ldcg(&g_acc.k[tid - 32]);
    __syncthreads();

    if (tid < 32) { g_acc.r[tid] = 0.0; g_acc.k[tid] = 0.0; }
    if (tid == 0) g_acc.cnt = 0u;

    float a = -0.7978845608028654f / eta;
    float selfLocal = 0.f;
    for (int i2 = tid; i2 < n; i2 += TPB) {
        float qv = __ldg(q + i2);
        float sg = __ldg(sigt + __ldg(spec + i2));
        selfLocal += qv * qv * (a + 0.5641895835477563f / sg);
    }
    float selfSum = blockReduceF(selfLocal);
    if (tid == 0) {
        double sr = 0.0, sk = 0.0;
        #pragma unroll
        for (int tt = 0; tt < 32; ++tt) { sr += shd[tt]; sk += shd[32 + tt]; }
        const double COEF = 14.399645478425668;
        double E = 0.5 * COEF * (sr + (4.0 * M_PI / (double)vol) * sk + (double)selfSum);
        out[0] = (float)E;
    }
}

extern "C" void kernel_launch(void* const* d_in, const int* in_sizes, int n_in,
                              void* d_out, int out_size) {
    const float* pos  = (const float*)d_in[0];
    const float* cell = (const float*)d_in[1];
    const float* q    = (const float*)d_in[2];
    const float* sigt = (const float*)d_in[3];
    const int*   spec = (const int*)d_in[4];
    const int*   nsr  = (const int*)d_in[5];
    const int*   nkr  = (const int*)d_in[6];
    int n = in_sizes[0] / 3;

    int nt = (n + TS - 1) / TS;
    int nTilePairs = nt * (nt + 1) / 2;
    unsigned int total = NB_RECIP + nTilePairs;
    k_main<<<total, TPB>>>(pos, cell, q, sigt, spec, nsr, nkr,
                           (float*)d_out, n, total);
}